// round 10
// baseline (speedup 1.0000x reference)
#include <cuda_runtime.h>
#include <cuda_fp16.h>
#include <math.h>

// dims: VOCAB=32000 E=256 U=512 4U=2048 T=512 B=128
// LSTM: 8 clusters of 16 CTAs; CTA = 16 batch rows x 128 gate cols (32 units)
// h exchange via DSMEM st.async + mbarrier complete_tx (no L2 handshake).

__device__ __align__(16) __half g_embW[32000u * 2048u];  // emb@Wx+b, cols permuted u*4+gate
__device__ __align__(16) __half g_embh[32000u * 256u];   // emb fp16
__device__ __align__(16) __half g_Wxr[256 * 2048];       // Wx permuted fp16
__device__ __align__(16) __half g_Whr[512 * 2048];       // Wh permuted fp16
__device__ __align__(16) float  g_br[2048];
__device__ __align__(16) __half g_hbuf[128 * 512];       // final h only (for MLP)

static __device__ __forceinline__ unsigned su(const void* p) {
    return (unsigned)__cvta_generic_to_shared(p);
}
static __device__ __forceinline__ void ldsm4(unsigned* r, unsigned a) {
    asm volatile("ldmatrix.sync.aligned.m8n8.x4.shared.b16 {%0,%1,%2,%3}, [%4];\n"
        : "=r"(r[0]), "=r"(r[1]), "=r"(r[2]), "=r"(r[3]) : "r"(a));
}
static __device__ __forceinline__ void ldsm4t(unsigned* r, unsigned a) {
    asm volatile("ldmatrix.sync.aligned.m8n8.x4.trans.shared.b16 {%0,%1,%2,%3}, [%4];\n"
        : "=r"(r[0]), "=r"(r[1]), "=r"(r[2]), "=r"(r[3]) : "r"(a));
}
static __device__ __forceinline__ void mmaf(float* d, const unsigned* a, const unsigned* b) {
    asm volatile("mma.sync.aligned.m16n8k16.row.col.f32.f16.f16.f32 "
        "{%0,%1,%2,%3}, {%4,%5,%6,%7}, {%8,%9}, {%0,%1,%2,%3};\n"
        : "+f"(d[0]), "+f"(d[1]), "+f"(d[2]), "+f"(d[3])
        : "r"(a[0]), "r"(a[1]), "r"(a[2]), "r"(a[3]), "r"(b[0]), "r"(b[1]));
}
static __device__ __forceinline__ float tanh_ap(float x) {
    float r; asm("tanh.approx.f32 %0, %1;" : "=f"(r) : "f"(x)); return r;
}
static __device__ __forceinline__ float sig_ap(float x) {
    return fmaf(tanh_ap(0.5f * x), 0.5f, 0.5f);
}
#define CPA(dst, src) asm volatile("cp.async.ca.shared.global [%0], [%1], 16;\n" :: "r"(dst), "l"(src))

// ---------- prep: permute weights to fp16, convert emb ----------
__global__ void prep_kernel(const float* __restrict__ emb, const float* __restrict__ Wx,
                            const float* __restrict__ Wh, const float* __restrict__ b) {
    int tid = blockIdx.x * blockDim.x + threadIdx.x, nth = gridDim.x * blockDim.x;
    for (int i = tid; i < 32000 * 128; i += nth) {
        float2 v = *(const float2*)(emb + (size_t)i * 2);
        *(__half2*)(g_embh + (size_t)i * 2) = __floats2half2_rn(v.x, v.y);
    }
    for (int i = tid; i < 256 * 2048; i += nth) {
        int k = i >> 11, j = i & 2047, u = j >> 2, gt = j & 3;
        g_Wxr[i] = __float2half_rn(Wx[k * 2048 + gt * 512 + u]);
    }
    for (int i = tid; i < 512 * 2048; i += nth) {
        int k = i >> 11, j = i & 2047, u = j >> 2, gt = j & 3;
        g_Whr[i] = __float2half_rn(Wh[k * 2048 + gt * 512 + u]);
    }
    for (int i = tid; i < 2048; i += nth) { int u = i >> 2, gt = i & 3; g_br[i] = b[gt * 512 + u]; }
}

// ---------- embW = embh @ Wxr + br : CTA 128x128, K=256, cp.async double-buffered ----------
__global__ __launch_bounds__(256) void embw_gemm() {
    __shared__ __align__(16) __half As[2][128 * 40];
    __shared__ __align__(16) __half Bs[2][32 * 136];
    int tid = threadIdx.x, lane = tid & 31, w = tid >> 5, wm = w >> 2, wn = w & 3;
    int m0 = blockIdx.y * 128, n0 = blockIdx.x * 128;
    float acc[4][4][4];
    #pragma unroll
    for (int i = 0; i < 4; i++)
        #pragma unroll
        for (int j = 0; j < 4; j++)
            #pragma unroll
            for (int k = 0; k < 4; k++) acc[i][j][k] = 0.f;
    int q = lane >> 3, l7 = lane & 7;
    auto issue = [&](int kt, int buf) {
        int k0 = kt * 32;
        unsigned sAb = su(As[buf]), sBb = su(Bs[buf]);
        #pragma unroll
        for (int i = 0; i < 2; i++) {
            int idx = tid + i * 256; int r = idx >> 2, cc = (idx & 3) * 8;
            CPA(sAb + (unsigned)((r * 40 + cc) * 2), g_embh + (size_t)(m0 + r) * 256 + k0 + cc);
        }
        #pragma unroll
        for (int i = 0; i < 2; i++) {
            int idx = tid + i * 256; int r = idx >> 4, cc = (idx & 15) * 8;
            CPA(sBb + (unsigned)((r * 136 + cc) * 2), g_Wxr + (size_t)(k0 + r) * 2048 + n0 + cc);
        }
        asm volatile("cp.async.commit_group;\n");
    };
    issue(0, 0);
    for (int kt = 0; kt < 8; kt++) {
        int buf = kt & 1;
        if (kt < 7) { issue(kt + 1, buf ^ 1); asm volatile("cp.async.wait_group 1;\n"); }
        else        { asm volatile("cp.async.wait_group 0;\n"); }
        __syncthreads();
        unsigned sA = su(As[buf]), sB = su(Bs[buf]);
        #pragma unroll
        for (int ks = 0; ks < 2; ks++) {
            unsigned a[4][4], bb[2][4];
            #pragma unroll
            for (int mt = 0; mt < 4; mt++) {
                int r = wm * 64 + mt * 16 + (q & 1) * 8 + l7, c = ks * 16 + (q >> 1) * 8;
                ldsm4(a[mt], sA + (unsigned)((r * 40 + c) * 2));
            }
            #pragma unroll
            for (int n2 = 0; n2 < 2; n2++) {
                int r = ks * 16 + (q & 1) * 8 + l7, c = wn * 32 + n2 * 16 + (q >> 1) * 8;
                ldsm4t(bb[n2], sB + (unsigned)((r * 136 + c) * 2));
            }
            #pragma unroll
            for (int mt = 0; mt < 4; mt++) {
                mmaf(acc[mt][0], a[mt], bb[0]); mmaf(acc[mt][1], a[mt], bb[0] + 2);
                mmaf(acc[mt][2], a[mt], bb[1]); mmaf(acc[mt][3], a[mt], bb[1] + 2);
            }
        }
        __syncthreads();
    }
    #pragma unroll
    for (int mt = 0; mt < 4; mt++)
        #pragma unroll
        for (int nt = 0; nt < 4; nt++) {
            int r = m0 + wm * 64 + mt * 16 + (lane >> 2);
            int c = n0 + wn * 32 + nt * 8 + (lane & 3) * 2;
            float2 bv = *(const float2*)(g_br + c);
            *(__half2*)(g_embW + (size_t)r * 2048 + c) =
                __floats2half2_rn(acc[mt][nt][0] + bv.x, acc[mt][nt][1] + bv.y);
            *(__half2*)(g_embW + (size_t)(r + 8) * 2048 + c) =
                __floats2half2_rn(acc[mt][nt][2] + bv.x, acc[mt][nt][3] + bv.y);
        }
}

// ---------- recurrence: 16-CTA clusters, DSMEM h exchange ----------
// smem: whs [512][136] (init only) | hs x2 [16][520] | zs [16][132] | mbar x2
#define OFF_HS   139264
#define HS_BYTES 16640
#define OFF_ZS   172544
#define OFF_MB   180992
#define LSTM_SMEM 181024

__global__ __launch_bounds__(256, 1) void lstm_kernel(const int* __restrict__ sentence) {
    extern __shared__ __align__(16) char smem[];
    __half* whs = (__half*)smem;
    float*  zs  = (float*)(smem + OFF_ZS);
    int tid = threadIdx.x, lane = tid & 31, w = tid >> 5;
    int g = blockIdx.x >> 4, m = blockIdx.x & 15;
    int q = lane >> 3, l7 = lane & 7;
    const int r16 = tid >> 4, c8 = (tid & 15) << 3;
    const int b = r16, u0 = (tid & 15) << 1;

    // Wh slice -> smem (for B-fragment preload)
    #pragma unroll 4
    for (int i = 0; i < 32; i++) {
        int idx = tid + i * 256; int k = idx >> 4, c = (idx & 15) * 8;
        *(uint4*)(whs + k * 136 + c) = *(const uint4*)(g_Whr + (size_t)k * 2048 + m * 128 + c);
    }
    // zero hs buf1 (read at t=0)
    for (int i = tid; i < HS_BYTES / 16; i += 256)
        *(uint4*)(smem + OFF_HS + HS_BYTES + i * 16) = make_uint4(0, 0, 0, 0);
    // stage x(0) into zs
    {
        int tok = sentence[(g * 16 + r16) * 512];
        uint4 v = *(const uint4*)(g_embW + (size_t)tok * 2048 + m * 128 + c8);
        __half2* hp = (__half2*)&v; float* zp = zs + r16 * 132 + c8;
        #pragma unroll
        for (int i = 0; i < 4; i++) { float2 f = __half22float2(hp[i]); zp[2*i] = f.x; zp[2*i+1] = f.y; }
    }
    __syncthreads();

    // Wh B-fragments -> registers (time-invariant)
    unsigned Bf[32][4];
    {
        unsigned sW = su(whs);
        #pragma unroll
        for (int kk = 0; kk < 32; kk++) {
            int r = kk * 16 + (q & 1) * 8 + l7, c = w * 16 + (q >> 1) * 8;
            ldsm4t(Bf[kk], sW + (unsigned)((r * 136 + c) * 2));
        }
    }
    // mbarriers: count=1 (the local expect_tx arrive); expect phase 0 on mbar0
    if (tid == 0) {
        asm volatile("mbarrier.init.shared.b64 [%0], 1;" :: "r"(su(smem + OFF_MB)));
        asm volatile("mbarrier.init.shared.b64 [%0], 1;" :: "r"(su(smem + OFF_MB + 8)));
        asm volatile("mbarrier.arrive.expect_tx.shared.b64 _, [%0], 16384;"
                     :: "r"(su(smem + OFF_MB)) : "memory");
    }
    __syncthreads();
    asm volatile("barrier.cluster.arrive.aligned;" ::: "memory");
    asm volatile("barrier.cluster.wait.aligned;" ::: "memory");

    const unsigned sbase = su(smem);
    const unsigned offH = (unsigned)((b * 520 + m * 32 + u0) * 2);  // payload offset in hs buf
    float cst0 = 0.f, cst1 = 0.f;

    for (int t = 0; t < 512; t++) {
        if (t) { // wait phase t-1 on mbar[(t-1)&1]
            unsigned mb = sbase + OFF_MB + (unsigned)(((t - 1) & 1) * 8);
            unsigned par = (unsigned)(((t - 1) >> 1) & 1);
            asm volatile(
                "{\n\t.reg .pred P1;\n"
                "WAIT_%=:\n\t"
                "mbarrier.try_wait.parity.acquire.cluster.shared::cta.b64 P1, [%0], %1, 0x989680;\n\t"
                "@P1 bra.uni DONE_%=;\n\t"
                "bra.uni WAIT_%=;\n"
                "DONE_%=:\n\t}"
                :: "r"(mb), "r"(par) : "memory");
        }
        // prefetch x(t+1)
        uint4 xv;
        { int tn = (t + 1 < 512) ? t + 1 : 511;
          int tok = sentence[(g * 16 + r16) * 512 + tn];
          xv = *(const uint4*)(g_embW + (size_t)tok * 2048 + m * 128 + c8); }
        // MMA from hs buf[(t-1)&1] (t=0 -> zeroed buf1)
        unsigned sH = sbase + OFF_HS + (unsigned)(((t + 1) & 1) * HS_BYTES);
        float acc[2][4] = {};
        #pragma unroll
        for (int kk = 0; kk < 32; kk++) {
            unsigned a[4];
            int r = (q & 1) * 8 + l7, c = kk * 16 + (q >> 1) * 8;
            ldsm4(a, sH + (unsigned)((r * 520 + c) * 2));
            mmaf(acc[0], a, Bf[kk]); mmaf(acc[1], a, Bf[kk] + 2);
        }
        { // accumulate h@Wh into zs (x already staged)
            int r = lane >> 2, c = w * 16 + (lane & 3) * 2;
            #pragma unroll
            for (int nf = 0; nf < 2; nf++) {
                zs[r * 132 + c + nf * 8]           += acc[nf][0];
                zs[r * 132 + c + nf * 8 + 1]       += acc[nf][1];
                zs[(r + 8) * 132 + c + nf * 8]     += acc[nf][2];
                zs[(r + 8) * 132 + c + nf * 8 + 1] += acc[nf][3];
            }
        }
        __syncthreads();
        { // gate epilogue
            const float* z0 = zs + b * 132 + u0 * 4;
            float i0 = sig_ap(z0[0]), f0 = sig_ap(z0[1]);
            float g0 = tanh_ap(z0[2]), o0 = sig_ap(z0[3]);
            cst0 = f0 * cst0 + i0 * g0;
            float h0 = o0 * tanh_ap(cst0);
            float i1 = sig_ap(z0[4]), f1 = sig_ap(z0[5]);
            float g1 = tanh_ap(z0[6]), o1 = sig_ap(z0[7]);
            cst1 = f1 * cst1 + i1 * g1;
            float h1 = o1 * tanh_ap(cst1);
            __half2 hh = __floats2half2_rn(h0, h1);
            unsigned hv = *(unsigned*)&hh;
            if (t < 511) {
                if (tid == 0) { // expect phase t+1 on mbar[(t+1)&1] BEFORE own sends
                    asm volatile("mbarrier.arrive.expect_tx.shared.b64 _, [%0], 16384;"
                                 :: "r"(sbase + OFF_MB + (unsigned)(((t + 1) & 1) * 8)) : "memory");
                }
                unsigned la = sbase + OFF_HS + (unsigned)((t & 1) * HS_BYTES) + offH;
                unsigned lm = sbase + OFF_MB + (unsigned)((t & 1) * 8);
                #pragma unroll
                for (int rk = 0; rk < 16; rk++) {
                    unsigned ra, rm;
                    asm("mapa.shared::cluster.u32 %0, %1, %2;" : "=r"(ra) : "r"(la), "r"(rk));
                    asm("mapa.shared::cluster.u32 %0, %1, %2;" : "=r"(rm) : "r"(lm), "r"(rk));
                    asm volatile(
                        "st.async.weak.shared::cluster.mbarrier::complete_tx::bytes.b32 [%0], %1, [%2];"
                        :: "r"(ra), "r"(hv), "r"(rm) : "memory");
                }
            } else {
                __stcg((unsigned*)(g_hbuf + (size_t)(g * 16 + b) * 512 + m * 32 + u0), hv);
            }
        }
        __syncthreads();
        if (t + 1 < 512) { // stage x(t+1) into zs
            __half2* hp = (__half2*)&xv; float* zp = zs + r16 * 132 + c8;
            #pragma unroll
            for (int i = 0; i < 4; i++) { float2 f = __half22float2(hp[i]); zp[2*i] = f.x; zp[2*i+1] = f.y; }
        }
        __syncthreads();
    }
    asm volatile("barrier.cluster.arrive.aligned;" ::: "memory");
    asm volatile("barrier.cluster.wait.aligned;" ::: "memory");
}

// ---------- MLP head ----------
__global__ void mlp_kernel(const float* __restrict__ W1, const float* __restrict__ b1,
                           const float* __restrict__ W2, const float* __restrict__ b2,
                           const float* __restrict__ W3, const float* __restrict__ b3,
                           float* __restrict__ out) {
    __shared__ float hr[512], h1[128], h2[64];
    int b = blockIdx.x, tid = threadIdx.x;
    #pragma unroll
    for (int i = 0; i < 4; i++)
        hr[tid + i * 128] = __half2float(g_hbuf[(size_t)b * 512 + tid + i * 128]);
    __syncthreads();
    float a0 = 0.f, a1 = 0.f, a2 = 0.f, a3 = 0.f;
    #pragma unroll 2
    for (int k = 0; k < 512; k += 4) {
        a0 = fmaf(hr[k],     W1[k * 128 + tid],       a0);
        a1 = fmaf(hr[k + 1], W1[(k + 1) * 128 + tid], a1);
        a2 = fmaf(hr[k + 2], W1[(k + 2) * 128 + tid], a2);
        a3 = fmaf(hr[k + 3], W1[(k + 3) * 128 + tid], a3);
    }
    h1[tid] = fmaxf(b1[tid] + (a0 + a1) + (a2 + a3), 0.f);
    __syncthreads();
    if (tid < 64) {
        float s0 = 0.f, s1 = 0.f;
        for (int k = 0; k < 128; k += 2) {
            s0 = fmaf(h1[k],     W2[k * 64 + tid],       s0);
            s1 = fmaf(h1[k + 1], W2[(k + 1) * 64 + tid], s1);
        }
        h2[tid] = fmaxf(b2[tid] + s0 + s1, 0.f);
    }
    __syncthreads();
    if (tid == 0) {
        float a3s = b3[0];
        for (int k = 0; k < 64; k++) a3s = fmaf(h2[k], W3[k], a3s);
        out[b] = 1.f / (1.f + __expf(-a3s));
    }
}

extern "C" void kernel_launch(void* const* d_in, const int* in_sizes, int n_in,
                              void* d_out, int out_size) {
    const int*   sentence = (const int*)d_in[0];
    const float* emb = (const float*)d_in[1];
    const float* Wx  = (const float*)d_in[2];
    const float* Wh  = (const float*)d_in[3];
    const float* b   = (const float*)d_in[4];
    const float* W1  = (const float*)d_in[5];
    const float* b1  = (const float*)d_in[6];
    const float* W2  = (const float*)d_in[7];
    const float* b2  = (const float*)d_in[8];
    const float* W3  = (const float*)d_in[9];
    const float* b3  = (const float*)d_in[10];
    float* out = (float*)d_out;

    cudaFuncSetAttribute(lstm_kernel, cudaFuncAttributeMaxDynamicSharedMemorySize, LSTM_SMEM);
    cudaFuncSetAttribute(lstm_kernel, cudaFuncAttributeNonPortableClusterSizeAllowed, 1);

    prep_kernel<<<512, 256>>>(emb, Wx, Wh, b);
    embw_gemm<<<dim3(16, 250), 256>>>();

    cudaLaunchConfig_t cfg = {};
    cfg.gridDim = dim3(128, 1, 1);
    cfg.blockDim = dim3(256, 1, 1);
    cfg.dynamicSmemBytes = LSTM_SMEM;
    cfg.stream = 0;
    cudaLaunchAttribute at[1];
    at[0].id = cudaLaunchAttributeClusterDimension;
    at[0].val.clusterDim.x = 16; at[0].val.clusterDim.y = 1; at[0].val.clusterDim.z = 1;
    cfg.attrs = at; cfg.numAttrs = 1;
    cudaLaunchKernelEx(&cfg, lstm_kernel, sentence);

    mlp_kernel<<<128, 128>>>(W1, b1, W2, b2, W3, b3, out);
}

// round 11
// speedup vs baseline: 1.1914x; 1.1914x over previous
#include <cuda_runtime.h>
#include <cuda_fp16.h>
#include <math.h>

// dims: VOCAB=32000 E=256 U=512 4U=2048 T=512 B=128
// LSTM: 8 groups x 16 CTAs; CTA = 16 batch x 128 gate cols (32 units)
// Gate-col permutation matches mma acc fragment: unit u=w*4+(lane&3),
// cols j,j+1 = i,f ; j+8,j+9 = g,o (j=(lane&3)*2). Epilogue fully in regs.

__device__ __align__(16) __half g_embW[32000u * 2048u];  // emb@Wx+b, frag-permuted cols
__device__ __align__(16) __half g_embh[32000u * 256u];   // emb fp16
__device__ __align__(16) __half g_Wxr[256 * 2048];       // Wx frag-permuted fp16
__device__ __align__(16) __half g_Whr[512 * 2048];       // Wh frag-permuted fp16
__device__ __align__(16) float  g_br[2048];
__device__ __align__(16) __half g_hbuf[2 * 128 * 512];   // double-buffered h
__device__ unsigned g_cnt[8];

static __device__ __forceinline__ unsigned su(const void* p) {
    return (unsigned)__cvta_generic_to_shared(p);
}
static __device__ __forceinline__ void ldsm4(unsigned* r, unsigned a) {
    asm volatile("ldmatrix.sync.aligned.m8n8.x4.shared.b16 {%0,%1,%2,%3}, [%4];\n"
        : "=r"(r[0]), "=r"(r[1]), "=r"(r[2]), "=r"(r[3]) : "r"(a));
}
static __device__ __forceinline__ void ldsm4t(unsigned* r, unsigned a) {
    asm volatile("ldmatrix.sync.aligned.m8n8.x4.trans.shared.b16 {%0,%1,%2,%3}, [%4];\n"
        : "=r"(r[0]), "=r"(r[1]), "=r"(r[2]), "=r"(r[3]) : "r"(a));
}
static __device__ __forceinline__ void mmaf(float* d, const unsigned* a, const unsigned* b) {
    asm volatile("mma.sync.aligned.m16n8k16.row.col.f32.f16.f16.f32 "
        "{%0,%1,%2,%3}, {%4,%5,%6,%7}, {%8,%9}, {%0,%1,%2,%3};\n"
        : "+f"(d[0]), "+f"(d[1]), "+f"(d[2]), "+f"(d[3])
        : "r"(a[0]), "r"(a[1]), "r"(a[2]), "r"(a[3]), "r"(b[0]), "r"(b[1]));
}
static __device__ __forceinline__ float tanh_ap(float x) {
    float r; asm("tanh.approx.f32 %0, %1;" : "=f"(r) : "f"(x)); return r;
}
static __device__ __forceinline__ float sig_ap(float x) {
    return fmaf(tanh_ap(0.5f * x), 0.5f, 0.5f);
}
#define CPA(dst, src) asm volatile("cp.async.ca.shared.global [%0], [%1], 16;\n" :: "r"(dst), "l"(src))
#define CPG(dst, src) asm volatile("cp.async.cg.shared.global [%0], [%1], 16;\n" :: "r"(dst), "l"(src))

// ---------- prep: fragment-permute weights to fp16, convert emb, zero state ----------
__global__ void prep_kernel(const float* __restrict__ emb, const float* __restrict__ Wx,
                            const float* __restrict__ Wh, const float* __restrict__ b) {
    int tid = blockIdx.x * blockDim.x + threadIdx.x, nth = gridDim.x * blockDim.x;
    for (int i = tid; i < 32000 * 128; i += nth) {
        float2 v = *(const float2*)(emb + (size_t)i * 2);
        *(__half2*)(g_embh + (size_t)i * 2) = __floats2half2_rn(v.x, v.y);
    }
    // permuted col p -> (gate, unit): m=p>>7, r=p&127, w=r>>4, t2=r&15
    // gate = (t2>>3)*2 + (t2&1), s=(t2&7)>>1, unit = m*32 + w*4 + s
    for (int i = tid; i < 256 * 2048; i += nth) {
        int k = i >> 11, p = i & 2047;
        int m = p >> 7, r = p & 127, w = r >> 4, t2 = r & 15;
        int gate = (t2 >> 3) * 2 + (t2 & 1), s = (t2 & 7) >> 1;
        g_Wxr[i] = __float2half_rn(Wx[k * 2048 + gate * 512 + m * 32 + w * 4 + s]);
    }
    for (int i = tid; i < 512 * 2048; i += nth) {
        int k = i >> 11, p = i & 2047;
        int m = p >> 7, r = p & 127, w = r >> 4, t2 = r & 15;
        int gate = (t2 >> 3) * 2 + (t2 & 1), s = (t2 & 7) >> 1;
        g_Whr[i] = __float2half_rn(Wh[k * 2048 + gate * 512 + m * 32 + w * 4 + s]);
    }
    for (int i = tid; i < 2048; i += nth) {
        int m = i >> 7, r = i & 127, w = r >> 4, t2 = r & 15;
        int gate = (t2 >> 3) * 2 + (t2 & 1), s = (t2 & 7) >> 1;
        g_br[i] = b[gate * 512 + m * 32 + w * 4 + s];
    }
    for (int i = tid; i < 2 * 128 * 512; i += nth) g_hbuf[i] = __float2half_rn(0.f);
    if (tid < 8) g_cnt[tid] = 0u;
}

// ---------- embW = embh @ Wxr + br : CTA 128x128, K=256, cp.async double-buffered ----------
__global__ __launch_bounds__(256) void embw_gemm() {
    __shared__ __align__(16) __half As[2][128 * 40];
    __shared__ __align__(16) __half Bs[2][32 * 136];
    int tid = threadIdx.x, lane = tid & 31, w = tid >> 5, wm = w >> 2, wn = w & 3;
    int m0 = blockIdx.y * 128, n0 = blockIdx.x * 128;
    float acc[4][4][4];
    #pragma unroll
    for (int i = 0; i < 4; i++)
        #pragma unroll
        for (int j = 0; j < 4; j++)
            #pragma unroll
            for (int k = 0; k < 4; k++) acc[i][j][k] = 0.f;
    int q = lane >> 3, l7 = lane & 7;
    auto issue = [&](int kt, int buf) {
        int k0 = kt * 32;
        unsigned sAb = su(As[buf]), sBb = su(Bs[buf]);
        #pragma unroll
        for (int i = 0; i < 2; i++) {
            int idx = tid + i * 256; int r = idx >> 2, cc = (idx & 3) * 8;
            CPA(sAb + (unsigned)((r * 40 + cc) * 2), g_embh + (size_t)(m0 + r) * 256 + k0 + cc);
        }
        #pragma unroll
        for (int i = 0; i < 2; i++) {
            int idx = tid + i * 256; int r = idx >> 4, cc = (idx & 15) * 8;
            CPA(sBb + (unsigned)((r * 136 + cc) * 2), g_Wxr + (size_t)(k0 + r) * 2048 + n0 + cc);
        }
        asm volatile("cp.async.commit_group;\n");
    };
    issue(0, 0);
    for (int kt = 0; kt < 8; kt++) {
        int buf = kt & 1;
        if (kt < 7) { issue(kt + 1, buf ^ 1); asm volatile("cp.async.wait_group 1;\n"); }
        else        { asm volatile("cp.async.wait_group 0;\n"); }
        __syncthreads();
        unsigned sA = su(As[buf]), sB = su(Bs[buf]);
        #pragma unroll
        for (int ks = 0; ks < 2; ks++) {
            unsigned a[4][4], bb[2][4];
            #pragma unroll
            for (int mt = 0; mt < 4; mt++) {
                int r = wm * 64 + mt * 16 + (q & 1) * 8 + l7, c = ks * 16 + (q >> 1) * 8;
                ldsm4(a[mt], sA + (unsigned)((r * 40 + c) * 2));
            }
            #pragma unroll
            for (int n2 = 0; n2 < 2; n2++) {
                int r = ks * 16 + (q & 1) * 8 + l7, c = wn * 32 + n2 * 16 + (q >> 1) * 8;
                ldsm4t(bb[n2], sB + (unsigned)((r * 136 + c) * 2));
            }
            #pragma unroll
            for (int mt = 0; mt < 4; mt++) {
                mmaf(acc[mt][0], a[mt], bb[0]); mmaf(acc[mt][1], a[mt], bb[0] + 2);
                mmaf(acc[mt][2], a[mt], bb[1]); mmaf(acc[mt][3], a[mt], bb[1] + 2);
            }
        }
        __syncthreads();
    }
    #pragma unroll
    for (int mt = 0; mt < 4; mt++)
        #pragma unroll
        for (int nt = 0; nt < 4; nt++) {
            int r = m0 + wm * 64 + mt * 16 + (lane >> 2);
            int c = n0 + wn * 32 + nt * 8 + (lane & 3) * 2;
            float2 bv = *(const float2*)(g_br + c);
            *(__half2*)(g_embW + (size_t)r * 2048 + c) =
                __floats2half2_rn(acc[mt][nt][0] + bv.x, acc[mt][nt][1] + bv.y);
            *(__half2*)(g_embW + (size_t)(r + 8) * 2048 + c) =
                __floats2half2_rn(acc[mt][nt][2] + bv.x, acc[mt][nt][3] + bv.y);
        }
}

// ---------- recurrence: persistent 128 CTAs, reg Wh + reg epilogue ----------
// smem: whs [512][136] (init only) | hs [16][520] at OFF_HS
#define OFF_HS 139264
#define LSTM_SMEM (OFF_HS + 16 * 1040)

__global__ __launch_bounds__(256, 1) void lstm_kernel(const int* __restrict__ sentence) {
    extern __shared__ __align__(16) char smem[];
    __half* whs = (__half*)smem;
    int tid = threadIdx.x, lane = tid & 31, w = tid >> 5;
    int g = blockIdx.x >> 4, m = blockIdx.x & 15;
    int q = lane >> 3, l7 = lane & 7;

    #pragma unroll 4
    for (int i = 0; i < 32; i++) {
        int idx = tid + i * 256; int k = idx >> 4, c = (idx & 15) * 8;
        *(uint4*)(whs + k * 136 + c) = *(const uint4*)(g_Whr + (size_t)k * 2048 + m * 128 + c);
    }
    __syncthreads();

    // Wh B-fragments -> registers (time-invariant)
    unsigned Bf[32][4];
    {
        unsigned sW = su(whs);
        #pragma unroll
        for (int kk = 0; kk < 32; kk++) {
            int r = kk * 16 + (q & 1) * 8 + l7, c = w * 16 + (q >> 1) * 8;
            ldsm4t(Bf[kk], sW + (unsigned)((r * 136 + c) * 2));
        }
    }
    const unsigned sH = su(smem + OFF_HS);
    // per-thread epilogue mapping
    const int b0 = lane >> 2, b1 = b0 + 8;
    const int sb0 = (g * 16 + b0) * 512, sb1 = (g * 16 + b1) * 512;
    const int xcol = m * 128 + w * 16 + (lane & 3) * 2;
    const int ug = m * 32 + w * 4 + (lane & 3);
    float cst0 = 0.f, cst1 = 0.f;

    // x(0) current regs
    unsigned xc[4];
    {
        const __half* p0 = g_embW + (size_t)sentence[sb0] * 2048 + xcol;
        const __half* p1 = g_embW + (size_t)sentence[sb1] * 2048 + xcol;
        xc[0] = *(const unsigned*)p0; xc[1] = *(const unsigned*)(p0 + 8);
        xc[2] = *(const unsigned*)p1; xc[3] = *(const unsigned*)(p1 + 8);
    }

    for (int t = 0; t < 512; t++) {
        if (t && lane == 0) {
            unsigned tgt = 16u * (unsigned)t, v;
            do { asm volatile("ld.acquire.gpu.global.u32 %0, [%1];" : "=r"(v) : "l"(&g_cnt[g])); } while (v < tgt);
        }
        __syncwarp();
        // stage h(t) via cp.async.cg (L2, no L1)
        const __half* hsrc = g_hbuf + (size_t)(t & 1) * 65536 + (size_t)g * 16 * 512;
        #pragma unroll
        for (int i = 0; i < 4; i++) {
            int idx = tid + i * 256; int r = idx >> 6, cw = idx & 63;
            CPG(sH + (unsigned)(r * 1040 + cw * 16), hsrc + r * 512 + cw * 8);
        }
        asm volatile("cp.async.commit_group;\n");
        // prefetch x(t+1)
        unsigned xn[4];
        {
            int tn = (t + 1 < 512) ? t + 1 : 511;
            const __half* p0 = g_embW + (size_t)sentence[sb0 + tn] * 2048 + xcol;
            const __half* p1 = g_embW + (size_t)sentence[sb1 + tn] * 2048 + xcol;
            xn[0] = *(const unsigned*)p0; xn[1] = *(const unsigned*)(p0 + 8);
            xn[2] = *(const unsigned*)p1; xn[3] = *(const unsigned*)(p1 + 8);
        }
        asm volatile("cp.async.wait_group 0;\n");
        __syncthreads();
        // MMA: z rows=batch, cols=permuted gate cols
        float acc[2][4] = {};
        #pragma unroll
        for (int kk = 0; kk < 32; kk++) {
            unsigned a[4];
            int r = (q & 1) * 8 + l7, c = kk * 16 + (q >> 1) * 8;
            ldsm4(a, sH + (unsigned)(r * 1040 + c * 2));
            mmaf(acc[0], a, Bf[kk]); mmaf(acc[1], a, Bf[kk] + 2);
        }
        // epilogue fully in registers: acc[0][0,1]=i,f(b0) acc[1][0,1]=g,o(b0); [2,3]=b1
        {
            float2 xa = __half22float2(*(__half2*)&xc[0]);
            float2 xb = __half22float2(*(__half2*)&xc[1]);
            float zi = acc[0][0] + xa.x, zf = acc[0][1] + xa.y;
            float zg = acc[1][0] + xb.x, zo = acc[1][1] + xb.y;
            cst0 = sig_ap(zf) * cst0 + sig_ap(zi) * tanh_ap(zg);
            float h0 = sig_ap(zo) * tanh_ap(cst0);
            xa = __half22float2(*(__half2*)&xc[2]);
            xb = __half22float2(*(__half2*)&xc[3]);
            zi = acc[0][2] + xa.x; zf = acc[0][3] + xa.y;
            zg = acc[1][2] + xb.x; zo = acc[1][3] + xb.y;
            cst1 = sig_ap(zf) * cst1 + sig_ap(zi) * tanh_ap(zg);
            float h1 = sig_ap(zo) * tanh_ap(cst1);
            __half* hdst = g_hbuf + (size_t)((t + 1) & 1) * 65536;
            unsigned short u0 = __half_as_ushort(__float2half_rn(h0));
            unsigned short u1 = __half_as_ushort(__float2half_rn(h1));
            asm volatile("st.global.cg.u16 [%0], %1;" :: "l"(hdst + sb0 + ug), "h"(u0) : "memory");
            asm volatile("st.global.cg.u16 [%0], %1;" :: "l"(hdst + sb1 + ug), "h"(u1) : "memory");
        }
        xc[0] = xn[0]; xc[1] = xn[1]; xc[2] = xn[2]; xc[3] = xn[3];
        __syncthreads();
        if (tid == 0)
            asm volatile("red.release.gpu.global.add.u32 [%0], %1;" :: "l"(&g_cnt[g]), "r"(1u) : "memory");
    }
}

// ---------- MLP head: 8 blocks x 16 batches (W1 read 8x, not 128x) ----------
__global__ __launch_bounds__(256) void mlp_kernel(
        const float* __restrict__ W1, const float* __restrict__ b1,
        const float* __restrict__ W2, const float* __restrict__ b2,
        const float* __restrict__ W3, const float* __restrict__ b3,
        float* __restrict__ out) {
    __shared__ float hr[16][512];
    __shared__ float h1s[16][128];
    __shared__ float h2s[16][64];
    int blk = blockIdx.x, tid = threadIdx.x;
    #pragma unroll
    for (int i = 0; i < 32; i++) {
        int idx = tid + i * 256; int b = idx >> 9, k = idx & 511;
        hr[b][k] = __half2float(g_hbuf[(size_t)(blk * 16 + b) * 512 + k]);
    }
    __syncthreads();
    {
        int n = tid & 127, hb = (tid >> 7) * 8;
        float a[8];
        #pragma unroll
        for (int i = 0; i < 8; i++) a[i] = b1[n];
        for (int k = 0; k < 512; k++) {
            float wv = W1[k * 128 + n];
            #pragma unroll
            for (int i = 0; i < 8; i++) a[i] = fmaf(hr[hb + i][k], wv, a[i]);
        }
        #pragma unroll
        for (int i = 0; i < 8; i++) h1s[hb + i][n] = fmaxf(a[i], 0.f);
    }
    __syncthreads();
    {
        int n = tid & 63, hb = (tid >> 6) * 4;
        float a[4];
        #pragma unroll
        for (int i = 0; i < 4; i++) a[i] = b2[n];
        for (int k = 0; k < 128; k++) {
            float wv = W2[k * 64 + n];
            #pragma unroll
            for (int i = 0; i < 4; i++) a[i] = fmaf(h1s[hb + i][k], wv, a[i]);
        }
        #pragma unroll
        for (int i = 0; i < 4; i++) h2s[hb + i][n] = fmaxf(a[i], 0.f);
    }
    __syncthreads();
    if (tid < 16) {
        float a = b3[0];
        for (int k = 0; k < 64; k++) a = fmaf(h2s[tid][k], W3[k], a);
        out[blk * 16 + tid] = 1.f / (1.f + __expf(-a));
    }
}

extern "C" void kernel_launch(void* const* d_in, const int* in_sizes, int n_in,
                              void* d_out, int out_size) {
    const int*   sentence = (const int*)d_in[0];
    const float* emb = (const float*)d_in[1];
    const float* Wx  = (const float*)d_in[2];
    const float* Wh  = (const float*)d_in[3];
    const float* b   = (const float*)d_in[4];
    const float* W1  = (const float*)d_in[5];
    const float* b1  = (const float*)d_in[6];
    const float* W2  = (const float*)d_in[7];
    const float* b2  = (const float*)d_in[8];
    const float* W3  = (const float*)d_in[9];
    const float* b3  = (const float*)d_in[10];
    float* out = (float*)d_out;
    cudaFuncSetAttribute(lstm_kernel, cudaFuncAttributeMaxDynamicSharedMemorySize, LSTM_SMEM);
    prep_kernel<<<512, 256>>>(emb, Wx, Wh, b);
    embw_gemm<<<dim3(16, 250), 256>>>();
    lstm_kernel<<<128, 256, LSTM_SMEM>>>(sentence);
    mlp_kernel<<<8, 256>>>(W1, b1, W2, b2, W3, b3, out);
}